// round 14
// baseline (speedup 1.0000x reference)
#include <cuda_runtime.h>
#include <cstdint>

#define BT   65536
#define KM   31
#define BLK  128
#define ROWS 384          // 3 rows/thread
#define NTX  171          // ceil(65536/384)
#define KCH  4

typedef unsigned long long ull;

__device__ float g_xt[32 * BT];
__device__ float g_wt[KM * 2048];
// slab: W1T 0(768) | B1 768 | W2T 792 | B2 1368 | W3T 1392 | B3 1968 | W4T 1992 | B4 2040

__device__ __forceinline__ ull ffma2(ull a, ull b, ull c) {
    ull d; asm("fma.rn.f32x2 %0, %1, %2, %3;" : "=l"(d) : "l"(a), "l"(b), "l"(c)); return d;
}
__device__ __forceinline__ ull fmul2(ull a, ull b) {
    ull d; asm("mul.rn.f32x2 %0, %1, %2;" : "=l"(d) : "l"(a), "l"(b)); return d;
}
__device__ __forceinline__ ull dup2(float a) {
    ull d; asm("mov.b64 %0, {%1, %1};" : "=l"(d) : "f"(a)); return d;
}
__device__ __forceinline__ ull dup_lo(ull v) {
    ull d; asm("{\n\t.reg .b32 l, h;\n\tmov.b64 {l, h}, %1;\n\tmov.b64 %0, {l, l};\n\t}"
               : "=l"(d) : "l"(v)); return d;
}
__device__ __forceinline__ ull dup_hi(ull v) {
    ull d; asm("{\n\t.reg .b32 l, h;\n\tmov.b64 {l, h}, %1;\n\tmov.b64 %0, {h, h};\n\t}"
               : "=l"(d) : "l"(v)); return d;
}
__device__ __forceinline__ void unpack2(ull v, float& lo, float& hi) {
    asm("mov.b64 {%0, %1}, %2;" : "=f"(lo), "=f"(hi) : "l"(v));
}
// packed LeakyReLU(0.2): 0.6*v + 0.4*|v|  (exact to ~1 ulp; validated R4)
__device__ __forceinline__ ull lrelu2(ull v) {
    const ull C06 = 0x3F19999A3F19999AULL;
    const ull C04 = 0x3ECCCCCD3ECCCCCDULL;
    const ull MSK = 0x7FFFFFFF7FFFFFFFULL;
    return ffma2(C04, v & MSK, fmul2(C06, v));
}

__device__ __forceinline__ uint32_t smem_u32(const void* p) {
    uint32_t a;
    asm("{ .reg .u64 t; cvta.to.shared.u64 t, %1; cvt.u32.u64 %0, t; }" : "=r"(a) : "l"(p));
    return a;
}
__device__ __forceinline__ void cp16(uint32_t dst, const void* src) {
    asm volatile("cp.async.cg.shared.global [%0], [%1], 16;" :: "r"(dst), "l"(src));
}
__device__ __forceinline__ void cp_commit() {
    asm volatile("cp.async.commit_group;" ::: "memory");
}
template <int N>
__device__ __forceinline__ void cp_wait() {
    asm volatile("cp.async.wait_group %0;" :: "n"(N) : "memory");
}

// smem float offsets
#define XS   0                    // x slice [j][384]
#define WS   (32 * ROWS)          // 12288: two 2048-float slabs
#define SMF  (WS + 2 * 2048)      // 16384 floats = 65536 B

// 24->24 for 3 rows, pre-act in / pre-act out, lrelu fused at consumption
__device__ __forceinline__ void layer24f3(const ull (*P)[12], ull (*Q)[12],
                                          const float* wt, const float* bias)
{
    const ull* bp = (const ull*)bias;
    #pragma unroll
    for (int p = 0; p < 12; ++p) {
        const ull b = bp[p];
        #pragma unroll
        for (int r = 0; r < 3; ++r) Q[r][p] = b;
    }
    #pragma unroll
    for (int hp = 0; hp < 12; ++hp) {
        ull de[3], dh[3];
        #pragma unroll
        for (int r = 0; r < 3; ++r) {
            const ull a = lrelu2(P[r][hp]);
            de[r] = dup_lo(a); dh[r] = dup_hi(a);
        }
        const ulonglong2* we = (const ulonglong2*)(wt + (2*hp)     * 24);
        const ulonglong2* wo = (const ulonglong2*)(wt + (2*hp + 1) * 24);
        #pragma unroll
        for (int q = 0; q < 6; ++q) {
            const ulonglong2 a = we[q];
            #pragma unroll
            for (int r = 0; r < 3; ++r) {
                Q[r][2*q]   = ffma2(a.x, de[r], Q[r][2*q]);
                Q[r][2*q+1] = ffma2(a.y, de[r], Q[r][2*q+1]);
            }
            const ulonglong2 b = wo[q];
            #pragma unroll
            for (int r = 0; r < 3; ++r) {
                Q[r][2*q]   = ffma2(b.x, dh[r], Q[r][2*q]);
                Q[r][2*q+1] = ffma2(b.y, dh[r], Q[r][2*q+1]);
            }
        }
    }
}

// ---------------- kernel 1: prep (unchanged) ----------------
__global__ void prep_kernel(const float* __restrict__ x,
                            const float* __restrict__ p0,
                            const float* __restrict__ W1, const float* __restrict__ b1,
                            const float* __restrict__ W2, const float* __restrict__ b2,
                            const float* __restrict__ W3, const float* __restrict__ b3,
                            const float* __restrict__ W4, const float* __restrict__ b4,
                            float* __restrict__ out)
{
    __shared__ float tile[128 * 33];
    const int tid = threadIdx.x;

    if (blockIdx.x < 512) {
        const int base = blockIdx.x * 128;
        #pragma unroll
        for (int i = 0; i < 4; ++i) {
            const int idx = tid + i * 256;
            const int r  = idx >> 3;
            const int jc = idx & 7;
            const float4 v = ((const float4*)x)[(size_t)(base + r) * 8 + jc];
            tile[r * 33 + 4*jc + 0] = v.x;
            tile[r * 33 + 4*jc + 1] = v.y;
            tile[r * 33 + 4*jc + 2] = v.z;
            tile[r * 33 + 4*jc + 3] = v.w;
        }
        __syncthreads();
        #pragma unroll
        for (int i = 0; i < 16; ++i) {
            const int idx = tid + i * 256;
            const int j = idx >> 7;
            const int r = idx & 127;
            g_xt[j * BT + base + r] = tile[r * 33 + j];
        }
        if (tid < 128) {
            const float s0 = p0[0];
            out[(size_t)(base + tid) * 32 + 31] = tile[tid * 33] * expf(s0) + p0[1];
            out[(size_t)BT * 32 + base + tid] = s0;
        }
    } else {
        const int k = blockIdx.x - 512;
        float* dst = g_wt + k * 2048;
        for (int i = tid; i < 768; i += 256) {
            const int h = i >> 5, j = i & 31;
            dst[j * 24 + h] = W1[k * 768 + i];
        }
        for (int i = tid; i < 576; i += 256)
            dst[792 + (i % 24) * 24 + (i / 24)] = W2[k * 576 + i];
        for (int i = tid; i < 576; i += 256)
            dst[1392 + (i % 24) * 24 + (i / 24)] = W3[k * 576 + i];
        for (int i = tid; i < 48; i += 256)
            dst[1992 + (i % 24) * 2 + (i / 24)] = W4[k * 48 + i];
        if (tid < 24) {
            dst[768 + tid]  = b1[k * 24 + tid];
            dst[1368 + tid] = b2[k * 24 + tid];
            dst[1968 + tid] = b3[k * 24 + tid];
        }
        if (tid < 2) dst[2040 + tid] = b4[k * 2 + tid];
    }
}

// ---------------- kernel 2: main — (384-row tile, k-chunk) per block ----------------
__global__ __launch_bounds__(BLK, 3)
void maf_main(float* __restrict__ out)
{
    extern __shared__ __align__(16) float sm[];

    const int tid  = threadIdx.x;
    const int base = blockIdx.x * ROWS;
    const int k0   = blockIdx.y * KCH;
    const int k1   = (k0 + KCH < KM) ? (k0 + KCH) : KM;

    // ---- stage x cols 0..k1 (float4, clamped in-bounds for tail block) ----
    {
        const int total4 = (k1 + 1) * (ROWS / 4);
        for (int idx = tid; idx < total4; idx += BLK) {
            const int j  = idx / (ROWS / 4);
            const int r4 = idx - j * (ROWS / 4);
            int src = base + 4 * r4;
            if (src > BT - 4) src = BT - 4;          // tail clamp (values unused)
            const float4 v = *(const float4*)(g_xt + (size_t)j * BT + src);
            ((float4*)(sm + XS + j * ROWS))[r4] = v;
        }
    }

    // ---- prologue: cp.async slab k0 into buffer 0 ----
    const uint32_t ws_addr = smem_u32(sm + WS);
    {
        const float4* src = (const float4*)(g_wt + k0 * 2048);
        #pragma unroll
        for (int i = 0; i < 4; ++i) {
            const int idx = tid + i * BLK;
            cp16(ws_addr + idx * 16, src + idx);
        }
        cp_commit();
    }

    const int r0g = base + tid;
    const int r1g = base + tid + BLK;
    const int r2g = base + tid + 2 * BLK;

    for (int k = k0; k < k1; ++k) {
        const int cur = (k - k0) & 1;

        if (k + 1 < k1) {
            const float4* src = (const float4*)(g_wt + (k + 1) * 2048);
            const uint32_t dst = ws_addr + (1 - cur) * 2048 * 4;
            #pragma unroll
            for (int i = 0; i < 4; ++i) {
                const int idx = tid + i * BLK;
                cp16(dst + idx * 16, src + idx);
            }
            cp_commit();
            cp_wait<1>();
        } else {
            cp_wait<0>();
        }
        __syncthreads();

        const float* sw = sm + WS + cur * 2048;
        ull A[3][12], B[3][12];

        // ---- layer 1: (k+1) -> 24, pre-acts into A ----
        {
            const ull* bp = (const ull*)(sw + 768);
            #pragma unroll
            for (int p = 0; p < 12; ++p) {
                const ull b = bp[p];
                #pragma unroll
                for (int r = 0; r < 3; ++r) A[r][p] = b;
            }
            #pragma unroll 2
            for (int j = 0; j <= k; ++j) {
                const ull d0 = dup2(sm[XS + j * ROWS + tid]);
                const ull d1 = dup2(sm[XS + j * ROWS + tid + BLK]);
                const ull d2 = dup2(sm[XS + j * ROWS + tid + 2 * BLK]);
                const ulonglong2* w = (const ulonglong2*)(sw + j * 24);
                #pragma unroll
                for (int q = 0; q < 6; ++q) {
                    const ulonglong2 wq = w[q];
                    A[0][2*q]   = ffma2(wq.x, d0, A[0][2*q]);
                    A[1][2*q]   = ffma2(wq.x, d1, A[1][2*q]);
                    A[2][2*q]   = ffma2(wq.x, d2, A[2][2*q]);
                    A[0][2*q+1] = ffma2(wq.y, d0, A[0][2*q+1]);
                    A[1][2*q+1] = ffma2(wq.y, d1, A[1][2*q+1]);
                    A[2][2*q+1] = ffma2(wq.y, d2, A[2][2*q+1]);
                }
            }
        }

        // ---- layers 2 & 3 (ping-pong, lrelu fused) ----
        layer24f3(A, B, sw + 792,  sw + 1368);
        layer24f3(B, A, sw + 1392, sw + 1968);

        // ---- layer 4: 24 -> (s,t) ----
        ull st[3];
        {
            const ull b4v = *(const ull*)(sw + 2040);
            #pragma unroll
            for (int r = 0; r < 3; ++r) st[r] = b4v;
            const ull* w4 = (const ull*)(sw + 1992);
            #pragma unroll
            for (int hp = 0; hp < 12; ++hp) {
                const ull we = w4[2*hp], wo = w4[2*hp + 1];
                #pragma unroll
                for (int r = 0; r < 3; ++r) {
                    const ull a = lrelu2(A[r][hp]);
                    st[r] = ffma2(we, dup_lo(a), st[r]);
                    st[r] = ffma2(wo, dup_hi(a), st[r]);
                }
            }
        }

        // ---- epilogue (guarded for tail block) ----
        #pragma unroll
        for (int r = 0; r < 3; ++r) {
            const int gr = (r == 0) ? r0g : (r == 1) ? r1g : r2g;
            if (gr < BT) {
                float s, t;
                unpack2(st[r], s, t);
                const float xk = sm[XS + (k + 1) * ROWS + tid + r * BLK];
                out[(size_t)gr * 32 + (30 - k)] = xk * expf(s) + t;
                atomicAdd(out + (size_t)BT * 32 + gr, s);
            }
        }

        __syncthreads();
    }
}

extern "C" void kernel_launch(void* const* d_in, const int* in_sizes, int n_in,
                              void* d_out, int out_size)
{
    const float* x  = (const float*)d_in[0];
    const float* p0 = (const float*)d_in[1];
    const float* W1 = (const float*)d_in[2];
    const float* b1 = (const float*)d_in[3];
    const float* W2 = (const float*)d_in[4];
    const float* b2 = (const float*)d_in[5];
    const float* W3 = (const float*)d_in[6];
    const float* b3 = (const float*)d_in[7];
    const float* W4 = (const float*)d_in[8];
    const float* b4 = (const float*)d_in[9];
    float* out = (float*)d_out;

    const int smem_bytes = SMF * 4;
    cudaFuncSetAttribute(maf_main, cudaFuncAttributeMaxDynamicSharedMemorySize, smem_bytes);

    prep_kernel<<<512 + KM, 256>>>(x, p0, W1, b1, W2, b2, W3, b3, W4, b4, out);
    maf_main<<<dim3(NTX, (KM + KCH - 1) / KCH), BLK, smem_bytes>>>(out);
}